// round 16
// baseline (speedup 1.0000x reference)
#include <cuda_runtime.h>
#include <cuda_bf16.h>
#include <math.h>

// Problem constants: B=4, T=32, fH=64 (H=32 per half), W=64, C=64, NH=4, DK=16
// modes: 24 freq-rows (u=0..11, 20..31) x 12 cols (v=0..11) = 288, x 16 out-ch
#define NM 288
#define ROWF 4608   // NM*16 complex per (b,n,t)

// ---------------- device scratch (no allocation allowed) --------------------
__device__ float2 g_S1 [6291456];  // [bt=128][fh=64][v=12][c=64]
__device__ float2 g_XF [4718592];  // [xy=2][mode=288][bt=128][c=64]
__device__ float2 g_QF [2359296];  // [(b*4+n)*32+t][mode][o=16]
__device__ float2 g_KF [2359296];
__device__ float2 g_VXF[2359296];
__device__ float2 g_VYF[2359296];
__device__ float  g_SC [16384];    // [bn=16][p=32][q=32]
__device__ float2 g_MF [4718592];  // [bnp=512][half=2][mode][o=16]
__device__ float  g_G  [4096];     // normalized gaussian over 64x64

// packed f32x2 helpers
__device__ __forceinline__ unsigned long long pk2(float lo, float hi) {
    unsigned long long r;
    asm("mov.b64 %0, {%1, %2};" : "=l"(r) : "f"(lo), "f"(hi));
    return r;
}
__device__ __forceinline__ void upk2(unsigned long long v, float& lo, float& hi) {
    asm("mov.b64 {%0, %1}, %2;" : "=f"(lo), "=f"(hi) : "l"(v));
}
__device__ __forceinline__ void fma2(unsigned long long& acc, unsigned long long a, unsigned long long b) {
    asm("fma.rn.f32x2 %0, %1, %2, %0;" : "+l"(acc) : "l"(a), "l"(b));
}

// ---------------- K0: gaussian --------------------------------------------
__global__ void k0_init() {
    int tid = threadIdx.x; // 256
    __shared__ double red[256];
    double lsum = 0.0;
    float vals[16];
    #pragma unroll
    for (int k = 0; k < 16; k++) {
        int m = tid * 16 + k;
        double dx = (m >> 6) - 31.5, dy = (m & 63) - 31.5;
        double v = exp(-(dx * dx + dy * dy) / 50.0);
        vals[k] = (float)v; lsum += v;
    }
    red[tid] = lsum; __syncthreads();
    for (int s = 128; s > 0; s >>= 1) { if (tid < s) red[tid] += red[tid + s]; __syncthreads(); }
    double inv = 1.0 / red[0];
    #pragma unroll
    for (int k = 0; k < 16; k++) g_G[tid * 16 + k] = (float)(vals[k] * inv);
}

// ---------------- K1: DFT along W (64 -> 12), w/(64-w) pairing -------------
__global__ __launch_bounds__(256) void k1_wdft(const float* __restrict__ z) {
    __shared__ float zz[4096];
    __shared__ float2 tw[768];     // [y=12][w=64] packed (cos,sin)
    int btf = blockIdx.x;          // bt*64 + fh  (0..8191)
    int tid = threadIdx.x;
    const float4* zp = (const float4*)(z + (size_t)btf * 4096);
    float4* zs = (float4*)zz;
    for (int i = tid; i < 1024; i += 256) zs[i] = zp[i];
    for (int i = tid; i < 768; i += 256) {
        int y = i >> 6, w = i & 63;
        float ang = (float)((w * y) & 63) * (1.0f / 32.0f);   // units of pi
        tw[i] = make_float2(cospif(ang), sinpif(ang));
    }
    __syncthreads();
    int c = tid & 63, yg = tid >> 6;   // y = yg*3 + j
    // singles: w=0 (t=1) and w=32 (t=(-1)^y)
    float v0 = zz[c], v32 = zz[32 * 64 + c];
    float2 acc[3];
    #pragma unroll
    for (int j = 0; j < 3; j++) {
        int y = yg * 3 + j;
        acc[j] = make_float2(v0 + ((y & 1) ? -v32 : v32), 0.f);
    }
    // pairs w, 64-w: conj twiddles -> re += S*c, im -= D*s
    #pragma unroll 4
    for (int w = 1; w < 32; w++) {
        float a = zz[w * 64 + c];
        float b = zz[(64 - w) * 64 + c];
        float S = a + b, D = a - b;
        #pragma unroll
        for (int j = 0; j < 3; j++) {
            float2 t = tw[(yg * 3 + j) * 64 + w];
            acc[j].x += S * t.x;
            acc[j].y -= D * t.y;
        }
    }
    #pragma unroll
    for (int j = 0; j < 3; j++)
        g_S1[((size_t)btf * 12 + yg * 3 + j) * 64 + c] = acc[j];
}

// ---------------- K2: DFT along H (32 -> 24), h/(32-h) pairing -------------
__global__ __launch_bounds__(256) void k2_hdft() {
    __shared__ float2 sA[2048];        // [h=32][c=64]
    __shared__ float2 tw[768];         // [f=24][h=32] packed (cos,sin)
    int bt = blockIdx.x;               // 0..127
    int xyy = blockIdx.y;              // 0..23 : xy*12 + y
    int xy = xyy / 12, y = xyy % 12;
    int tid = threadIdx.x;
    for (int e = tid; e < 2048; e += 256) {
        int hl = e >> 6, c = e & 63;
        sA[e] = g_S1[((size_t)(bt * 64 + xy * 32 + hl) * 12 + y) * 64 + c];
    }
    for (int i = tid; i < 768; i += 256) {
        int f = i >> 5, h = i & 31;
        int fx = (f < 12) ? f : (f + 8);
        float ang = (float)((fx * h) & 31) * (1.0f / 16.0f);
        tw[i] = make_float2(cospif(ang), sinpif(ang));
    }
    __syncthreads();
    int c = tid & 63, fg = tid >> 6;   // f = fg*6 + j
    // singles: h=0 (t=1), h=16 (t=((-1)^u, 0))
    float2 a0 = sA[c], a16 = sA[16 * 64 + c];
    float2 acc[6];
    #pragma unroll
    for (int j = 0; j < 6; j++) {
        int f = fg * 6 + j;
        int fx = (f < 12) ? f : (f + 8);
        float sg = (fx & 1) ? -1.f : 1.f;
        acc[j] = make_float2(a0.x + sg * a16.x, a0.y + sg * a16.y);
    }
    // pairs h, 32-h: re += Sx*c + Dy*s ; im += Sy*c - Dx*s
    #pragma unroll 3
    for (int hl = 1; hl < 16; hl++) {
        float2 a = sA[hl * 64 + c];
        float2 b = sA[(32 - hl) * 64 + c];
        float Sx = a.x + b.x, Sy = a.y + b.y;
        float Dx = a.x - b.x, Dy = a.y - b.y;
        #pragma unroll
        for (int j = 0; j < 6; j++) {
            float2 t = tw[(fg * 6 + j) * 32 + hl];
            acc[j].x += Sx * t.x + Dy * t.y;
            acc[j].y += Sy * t.x - Dx * t.y;
        }
    }
    #pragma unroll
    for (int j = 0; j < 6; j++) {
        int f = fg * 6 + j;
        g_XF[((size_t)(xy * NM + f * 12 + y) * 128 + bt) * 64 + c] = acc[j];
    }
}

// ---------------- K3: per-mode complex channel mixing (bt-pair fma2) -------
// Full single-shot staging: Wpk 64KB + Apk 32KB + Ayp 16KB = 112KB dyn smem,
// ONE barrier, then a sync-free 64-ii reduction (2 CTAs/SM).
__global__ __launch_bounds__(256, 2) void k3_mix(const float* __restrict__ wq,
                                                 const float* __restrict__ wk,
                                                 const float* __restrict__ wvx,
                                                 const float* __restrict__ wvy) {
    extern __shared__ __align__(16) char dyn[];
    float4* Wpk = (float4*)dyn;                       // [i=64][oh=64] 64KB
    float4* Apk = (float4*)(dyn + 65536);             // [pr=32][ii=64] 32KB
    float2* Ayp = (float2*)(dyn + 65536 + 32768);     // [pr=32][ii=64] 16KB
    const ulonglong2* Wpk64 = (const ulonglong2*)Wpk;
    const ulonglong2* Apk64 = (const ulonglong2*)Apk;
    const unsigned long long* Ayp64 = (const unsigned long long*)Ayp;
    int mode = blockIdx.x;             // 0..287
    int wi   = blockIdx.y;             // 0..3
    int bth  = blockIdx.z;             // 0..1
    int xr = mode / 12, y = mode % 12;
    const float* wb = (wi == 0) ? wq : (wi == 1) ? wk : (wi == 2) ? wvx : wvy;
    int src = (wi == 3) ? 1 : 0;
    float2* outp = (wi == 0) ? g_QF : (wi == 1) ? g_KF : (wi == 2) ? g_VXF : g_VYF;
    int ri = (xr < 12) ? 0 : 1;
    int xx = (xr < 12) ? xr : xr - 12;
    // weight layout [region2][reim2][i=64][o=16][x=12][y=12][h=4]
    size_t moff = (size_t)ri * 1179648 + (size_t)xx * 48 + (size_t)y * 4;
    int tid = threadIdx.x;
    for (int e2 = tid; e2 < 1024; e2 += 256) {
        int i = e2 >> 4, o = e2 & 15;
        size_t a = moff + (size_t)i * 9216 + (size_t)o * 576;   // 16B aligned, 4 heads
        float4 rv = *(const float4*)&wb[a];
        float4 iv = *(const float4*)&wb[a + 589824];
        Wpk[i * 64 +  0 + o] = make_float4(rv.x, rv.x, iv.x, iv.x);
        Wpk[i * 64 + 16 + o] = make_float4(rv.y, rv.y, iv.y, iv.y);
        Wpk[i * 64 + 32 + o] = make_float4(rv.z, rv.z, iv.z, iv.z);
        Wpk[i * 64 + 48 + o] = make_float4(rv.w, rv.w, iv.w, iv.w);
    }
    const float2* xsrc = g_XF + (size_t)(src * NM + mode) * 8192 + (size_t)bth * 4096;
    // stage ALL activations once: 2048 (pr, ii) entries, 8 per thread
    for (int e = tid; e < 2048; e += 256) {
        int pr = e >> 6, ii = e & 63;
        float2 a0 = xsrc[(size_t)(pr * 2 + 0) * 64 + ii];
        float2 a1 = xsrc[(size_t)(pr * 2 + 1) * 64 + ii];
        Apk[pr * 64 + ii] = make_float4(a0.x, a1.x, -a0.y, -a1.y);
        Ayp[pr * 64 + ii] = make_float2(a0.y, a1.y);
    }
    __syncthreads();
    int ohq = tid & 15;                // o index; h = k strided by 16
    int pairq = tid >> 4;              // 0..15 -> handles pairs pairq*2, pairq*2+1
    unsigned long long accRe[4][2], accIm[4][2];
    #pragma unroll
    for (int k = 0; k < 4; k++)
        #pragma unroll
        for (int p = 0; p < 2; p++) { accRe[k][p] = 0ull; accIm[k][p] = 0ull; }
    #pragma unroll 4
    for (int ii = 0; ii < 64; ii++) {
        ulonglong2 w0 = Wpk64[ii * 64 + ohq];        // .x=(wx,wx) .y=(wy,wy)
        ulonglong2 w1 = Wpk64[ii * 64 + ohq + 16];
        ulonglong2 w2 = Wpk64[ii * 64 + ohq + 32];
        ulonglong2 w3 = Wpk64[ii * 64 + ohq + 48];
        #pragma unroll
        for (int p = 0; p < 2; p++) {
            ulonglong2 a = Apk64[(pairq * 2 + p) * 64 + ii];  // .x=(ax0,ax1) .y=(-ay0,-ay1)
            unsigned long long ap = Ayp64[(pairq * 2 + p) * 64 + ii]; // (ay0,ay1)
            fma2(accRe[0][p], a.x, w0.x); fma2(accRe[0][p], a.y, w0.y);
            fma2(accIm[0][p], a.x, w0.y); fma2(accIm[0][p], ap,  w0.x);
            fma2(accRe[1][p], a.x, w1.x); fma2(accRe[1][p], a.y, w1.y);
            fma2(accIm[1][p], a.x, w1.y); fma2(accIm[1][p], ap,  w1.x);
            fma2(accRe[2][p], a.x, w2.x); fma2(accRe[2][p], a.y, w2.y);
            fma2(accIm[2][p], a.x, w2.y); fma2(accIm[2][p], ap,  w2.x);
            fma2(accRe[3][p], a.x, w3.x); fma2(accRe[3][p], a.y, w3.y);
            fma2(accIm[3][p], a.x, w3.y); fma2(accIm[3][p], ap,  w3.x);
        }
    }
    #pragma unroll
    for (int p = 0; p < 2; p++) {
        int pr = pairq * 2 + p;
        #pragma unroll
        for (int k = 0; k < 4; k++) {    // h = k, o = ohq
            float re0, re1, im0, im1;
            upk2(accRe[k][p], re0, re1);
            upk2(accIm[k][p], im0, im1);
            int bt0 = bth * 64 + pr * 2;
            int b0 = bt0 >> 5, t0 = bt0 & 31;
            int bt1 = bt0 + 1;
            int b1 = bt1 >> 5, t1 = bt1 & 31;
            outp[((size_t)((b0 * 4 + k) * 32 + t0) * NM + mode) * 16 + ohq] = make_float2(re0, im0);
            outp[((size_t)((b1 * 4 + k) * 32 + t1) * NM + mode) * 16 + ohq] = make_float2(re1, im1);
        }
    }
}

// ---------------- K4: scores via Parseval (+ DC-column cross term) ---------
__global__ __launch_bounds__(256) void k4_scores() {
    __shared__ float2 sQ[3072];        // [pi=4][768] weighted Q chunk (24KB)
    __shared__ float2 sQc[1536];       // [pi=4][384] cross-term Q      (12KB)
    int blk = blockIdx.x;              // 0..127
    int bn = blk >> 3, pg = blk & 7;
    int tid = threadIdx.x, lane = tid & 31, warp = tid >> 5;
    for (int e = tid; e < 1536; e += 256) {
        int pi = e / 384, r = e - pi * 384;
        int xr = r >> 4, o = r & 15;
        float2 v = make_float2(0.f, 0.f);
        if (xr != 12) {
            int pxr = (xr == 0) ? 0 : (24 - xr);
            float2 q = g_QF[(size_t)(bn * 32 + pg * 4 + pi) * ROWF + pxr * 192 + o];
            v = make_float2(0.5f * q.x, 0.5f * q.y);
        }
        sQc[e] = v;
    }
    float acc[4][4];
    #pragma unroll
    for (int pi = 0; pi < 4; pi++)
        #pragma unroll
        for (int qi = 0; qi < 4; qi++) acc[pi][qi] = 0.f;
    int q0 = warp * 4;
    for (int ch = 0; ch < 6; ch++) {
        __syncthreads();
        for (int e = tid; e < 3072; e += 256) {
            int pi = e / 768, r = e - pi * 768;
            int j = ch * 768 + r;
            float2 q = g_QF[(size_t)(bn * 32 + pg * 4 + pi) * ROWF + j];
            float w = (((j >> 4) % 12) == 0) ? 0.5f : 2.0f;
            sQ[e] = make_float2(q.x * w, q.y * w);
        }
        __syncthreads();
        #pragma unroll 4
        for (int r = lane; r < 768; r += 32) {
            int j = ch * 768 + r;
            float2 kk0 = g_KF[(size_t)(bn * 32 + q0 + 0) * ROWF + j];
            float2 kk1 = g_KF[(size_t)(bn * 32 + q0 + 1) * ROWF + j];
            float2 kk2 = g_KF[(size_t)(bn * 32 + q0 + 2) * ROWF + j];
            float2 kk3 = g_KF[(size_t)(bn * 32 + q0 + 3) * ROWF + j];
            #pragma unroll
            for (int pi = 0; pi < 4; pi++) {
                float2 qw = sQ[pi * 768 + r];
                acc[pi][0] += qw.x * kk0.x + qw.y * kk0.y;
                acc[pi][1] += qw.x * kk1.x + qw.y * kk1.y;
                acc[pi][2] += qw.x * kk2.x + qw.y * kk2.y;
                acc[pi][3] += qw.x * kk3.x + qw.y * kk3.y;
            }
        }
    }
    #pragma unroll 2
    for (int r = lane; r < 384; r += 32) {
        int xr = r >> 4, o = r & 15;
        size_t koff = (size_t)xr * 192 + o;
        float2 kk0 = g_KF[(size_t)(bn * 32 + q0 + 0) * ROWF + koff];
        float2 kk1 = g_KF[(size_t)(bn * 32 + q0 + 1) * ROWF + koff];
        float2 kk2 = g_KF[(size_t)(bn * 32 + q0 + 2) * ROWF + koff];
        float2 kk3 = g_KF[(size_t)(bn * 32 + q0 + 3) * ROWF + koff];
        #pragma unroll
        for (int pi = 0; pi < 4; pi++) {
            float2 qc = sQc[pi * 384 + r];
            acc[pi][0] += qc.x * kk0.x - qc.y * kk0.y;
            acc[pi][1] += qc.x * kk1.x - qc.y * kk1.y;
            acc[pi][2] += qc.x * kk2.x - qc.y * kk2.y;
            acc[pi][3] += qc.x * kk3.x - qc.y * kk3.y;
        }
    }
    #pragma unroll
    for (int pi = 0; pi < 4; pi++)
        #pragma unroll
        for (int qi = 0; qi < 4; qi++) {
            float s = acc[pi][qi];
            #pragma unroll
            for (int off = 16; off; off >>= 1) s += __shfl_down_sync(0xffffffffu, s, off);
            if (lane == 0)
                g_SC[bn * 1024 + (pg * 4 + pi) * 32 + q0 + qi] = s * (1.0f / (2048.0f * 4096.0f));
        }
}

// ---------------- K5: Fourier-domain T-mixing of V -------------------------
__global__ __launch_bounds__(256) void k5_mixv() {
    __shared__ float ssc[256];         // 8 p x 32 q
    int bn = blockIdx.x, half = blockIdx.y, pg = blockIdx.z;
    int tid = threadIdx.x;
    ssc[tid] = g_SC[bn * 1024 + pg * 256 + tid];
    __syncthreads();
    const float4* V = (const float4*)((half == 0) ? g_VXF : g_VYF);
    float4* MFp = (float4*)g_MF;       // row stride 2304 float4
    for (int ei = 0; ei < 9; ei++) {
        int e = tid + ei * 256;        // 0..2303
        float4 acc[8];
        #pragma unroll
        for (int pp = 0; pp < 8; pp++) acc[pp] = make_float4(0.f, 0.f, 0.f, 0.f);
        for (int q = 0; q < 32; q++) {
            float4 v = V[(size_t)(bn * 32 + q) * 2304 + e];
            #pragma unroll
            for (int pp = 0; pp < 8; pp++) {
                float s = ssc[pp * 32 + q];
                acc[pp].x += s * v.x; acc[pp].y += s * v.y;
                acc[pp].z += s * v.z; acc[pp].w += s * v.w;
            }
        }
        #pragma unroll
        for (int pp = 0; pp < 8; pp++) {
            int p = pg * 8 + pp;
            MFp[((size_t)(bn * 32 + p) * 2 + half) * 2304 + e] = acc[pp];
        }
    }
}

// ---------------- K6: inverse transform + gaussian, symmetry-paired --------
__global__ __launch_bounds__(256) void k6_inv(float* __restrict__ out) {
    __shared__ float2 Ms[2304];        // [f=24][v=12][oo=8]
    __shared__ float2 G[3072];         // [h=32][v=12][oo=8]
    __shared__ float2 cstab[32];
    __shared__ float wtc[64], wts[64];
    int bnp = blockIdx.x;              // 0..511 = (b*4+n)*32+p
    int half = blockIdx.y;             // 0..1
    int og = blockIdx.z;               // 0..1 (o-group of 8)
    int tid = threadIdx.x;
    if (tid < 64) { wtc[tid] = cospif(tid * (1.0f / 32.0f)); wts[tid] = sinpif(tid * (1.0f / 32.0f)); }
    else if (tid < 96) { int j = tid - 64; cstab[j] = make_float2(cospif(j * (1.0f / 16.0f)), sinpif(j * (1.0f / 16.0f))); }
    const float2* src = g_MF + ((size_t)bnp * 2 + half) * ROWF;
    for (int e = tid; e < 2304; e += 256) {
        int f = e / 96; int r = e - f * 96; int v = r >> 3; int oo = r & 7;
        Ms[e] = src[(f * 12 + v) * 16 + og * 8 + oo];
    }
    __syncthreads();
    // phase A: u-inverse with u <-> 32-u pairing (f=u pairs f=24-u, u=1..11;
    // singles f=0 (u=0) and f=12 (u=20)).
    #pragma unroll
    for (int r = 0; r < 3; r++) {
        int task = tid + r * 256;      // 768 tasks
        int oo = task & 7, v = (task >> 3) % 12, hg = task / 96;
        int h0 = hg * 4;
        // f=0: t=1 for all h
        float2 m0 = Ms[v * 8 + oo];
        float2 a0 = m0, a1 = m0, a2 = m0, a3 = m0;
        // f=12 single (u=20)
        {
            float2 m = Ms[12 * 96 + v * 8 + oo];
            float2 t0 = cstab[(20 * h0) & 31];
            float2 t1 = cstab[(20 * (h0 + 1)) & 31];
            float2 t2 = cstab[(20 * (h0 + 2)) & 31];
            float2 t3 = cstab[(20 * (h0 + 3)) & 31];
            a0.x += m.x*t0.x - m.y*t0.y; a0.y += m.x*t0.y + m.y*t0.x;
            a1.x += m.x*t1.x - m.y*t1.y; a1.y += m.x*t1.y + m.y*t1.x;
            a2.x += m.x*t2.x - m.y*t2.y; a2.y += m.x*t2.y + m.y*t2.x;
            a3.x += m.x*t3.x - m.y*t3.y; a3.y += m.x*t3.y + m.y*t3.x;
        }
        // pairs: u=1..11, partner f'=24-u (u'=32-u, conj twiddle)
        #pragma unroll
        for (int u = 1; u <= 11; u++) {
            float2 mA = Ms[u * 96 + v * 8 + oo];
            float2 mB = Ms[(24 - u) * 96 + v * 8 + oo];
            float Sx = mA.x + mB.x, Sy = mA.y + mB.y;
            float Dx = mA.x - mB.x, Dy = mA.y - mB.y;
            float2 t0 = cstab[(u * h0) & 31];
            float2 t1 = cstab[(u * (h0 + 1)) & 31];
            float2 t2 = cstab[(u * (h0 + 2)) & 31];
            float2 t3 = cstab[(u * (h0 + 3)) & 31];
            a0.x += Sx*t0.x - Dy*t0.y; a0.y += Dx*t0.y + Sy*t0.x;
            a1.x += Sx*t1.x - Dy*t1.y; a1.y += Dx*t1.y + Sy*t1.x;
            a2.x += Sx*t2.x - Dy*t2.y; a2.y += Dx*t2.y + Sy*t2.x;
            a3.x += Sx*t3.x - Dy*t3.y; a3.y += Dx*t3.y + Sy*t3.x;
        }
        float wv = (v == 0) ? (1.0f / 2048.0f) : (2.0f / 2048.0f);
        int base = h0 * 96 + v * 8 + oo;
        G[base      ] = make_float2(a0.x * wv, a0.y * wv);
        G[base +  96] = make_float2(a1.x * wv, a1.y * wv);
        G[base + 192] = make_float2(a2.x * wv, a2.y * wv);
        G[base + 288] = make_float2(a3.x * wv, a3.y * wv);
    }
    __syncthreads();
    // phase B: w-inverse via even/odd-v split (w+32 twiddle = (-1)^v * w twiddle)
    int oo = tid & 7;
    int wb = tid >> 3;                 // 0..31 ; covers w = wb and wb+32
    float tc[12], ts[12];
    #pragma unroll
    for (int v = 0; v < 12; v++) {
        tc[v] = wtc[(v * wb) & 63];
        ts[v] = wts[(v * wb) & 63];
    }
    size_t obase = (size_t)bnp * 65536 + og * 8 + oo;
    for (int h = 0; h < 32; h++) {
        float E = 0.f, O = 0.f;
        #pragma unroll
        for (int v = 0; v < 12; v += 2) {
            float2 ge = G[h * 96 + v * 8 + oo];
            E += ge.x * tc[v] - ge.y * ts[v];
            float2 go = G[h * 96 + (v + 1) * 8 + oo];
            O += go.x * tc[v + 1] - go.y * ts[v + 1];
        }
        float aw0 = E + O, aw1 = E - O;
        int m0 = (half * 32 + h) * 64 + wb;
        out[obase + (size_t)m0 * 16]        = aw0 * g_G[m0];
        out[obase + (size_t)(m0 + 32) * 16] = aw1 * g_G[m0 + 32];
    }
}

extern "C" void kernel_launch(void* const* d_in, const int* in_sizes, int n_in,
                              void* d_out, int out_size) {
    const float* z   = (const float*)d_in[0];
    const float* wq  = (const float*)d_in[1];
    const float* wk  = (const float*)d_in[2];
    const float* wvx = (const float*)d_in[3];
    const float* wvy = (const float*)d_in[4];
    float* out = (float*)d_out;
    (void)in_sizes; (void)n_in; (void)out_size;

    static int attr_done = 0;
    if (!attr_done) {
        cudaFuncSetAttribute(k3_mix, cudaFuncAttributeMaxDynamicSharedMemorySize, 114688);
        attr_done = 1;
    }

    k0_init<<<1, 256>>>();
    k1_wdft<<<8192, 256>>>(z);
    k2_hdft<<<dim3(128, 24), 256>>>();
    k3_mix<<<dim3(288, 4, 2), 256, 114688>>>(wq, wk, wvx, wvy);
    k4_scores<<<128, 256>>>();
    k5_mixv<<<dim3(16, 2, 4), 256>>>();
    k6_inv<<<dim3(512, 2, 2), 256>>>(out);
}

// round 17
// speedup vs baseline: 1.4429x; 1.4429x over previous
#include <cuda_runtime.h>
#include <cuda_bf16.h>
#include <math.h>

// Problem constants: B=4, T=32, fH=64 (H=32 per half), W=64, C=64, NH=4, DK=16
// modes: 24 freq-rows (u=0..11, 20..31) x 12 cols (v=0..11) = 288, x 16 out-ch
#define NM 288
#define ROWF 4608   // NM*16 complex per (b,n,t)

// ---------------- device scratch (no allocation allowed) --------------------
__device__ float2 g_S1 [6291456];  // [bt=128][fh=64][v=12][c=64]
__device__ float2 g_XF [4718592];  // [xy=2][mode=288][bt=128][c=64]
__device__ float2 g_QF [2359296];  // [(b*4+n)*32+t][mode][o=16]
__device__ float2 g_KF [2359296];
__device__ float2 g_VXF[2359296];
__device__ float2 g_VYF[2359296];
__device__ float  g_SC [16384];    // [bn=16][p=32][q=32]
__device__ float2 g_MF [4718592];  // [bnp=512][half=2][mode][o=16]
__device__ float  g_G  [4096];     // normalized gaussian over 64x64

// packed f32x2 helpers
__device__ __forceinline__ unsigned long long pk2(float lo, float hi) {
    unsigned long long r;
    asm("mov.b64 %0, {%1, %2};" : "=l"(r) : "f"(lo), "f"(hi));
    return r;
}
__device__ __forceinline__ void upk2(unsigned long long v, float& lo, float& hi) {
    asm("mov.b64 {%0, %1}, %2;" : "=f"(lo), "=f"(hi) : "l"(v));
}
__device__ __forceinline__ void fma2(unsigned long long& acc, unsigned long long a, unsigned long long b) {
    asm("fma.rn.f32x2 %0, %1, %2, %0;" : "+l"(acc) : "l"(a), "l"(b));
}

// ---------------- K0: gaussian --------------------------------------------
__global__ void k0_init() {
    int tid = threadIdx.x; // 256
    __shared__ double red[256];
    double lsum = 0.0;
    float vals[16];
    #pragma unroll
    for (int k = 0; k < 16; k++) {
        int m = tid * 16 + k;
        double dx = (m >> 6) - 31.5, dy = (m & 63) - 31.5;
        double v = exp(-(dx * dx + dy * dy) / 50.0);
        vals[k] = (float)v; lsum += v;
    }
    red[tid] = lsum; __syncthreads();
    for (int s = 128; s > 0; s >>= 1) { if (tid < s) red[tid] += red[tid + s]; __syncthreads(); }
    double inv = 1.0 / red[0];
    #pragma unroll
    for (int k = 0; k < 16; k++) g_G[tid * 16 + k] = (float)(vals[k] * inv);
}

// ---------------- K1: DFT along W (64 -> 12), w/(64-w) pairing -------------
__global__ __launch_bounds__(256) void k1_wdft(const float* __restrict__ z) {
    __shared__ float zz[4096];
    __shared__ float2 tw[768];     // [y=12][w=64] packed (cos,sin)
    int btf = blockIdx.x;          // bt*64 + fh  (0..8191)
    int tid = threadIdx.x;
    const float4* zp = (const float4*)(z + (size_t)btf * 4096);
    float4* zs = (float4*)zz;
    for (int i = tid; i < 1024; i += 256) zs[i] = zp[i];
    for (int i = tid; i < 768; i += 256) {
        int y = i >> 6, w = i & 63;
        float ang = (float)((w * y) & 63) * (1.0f / 32.0f);   // units of pi
        tw[i] = make_float2(cospif(ang), sinpif(ang));
    }
    __syncthreads();
    int c = tid & 63, yg = tid >> 6;   // y = yg*3 + j
    // singles: w=0 (t=1) and w=32 (t=(-1)^y)
    float v0 = zz[c], v32 = zz[32 * 64 + c];
    float2 acc[3];
    #pragma unroll
    for (int j = 0; j < 3; j++) {
        int y = yg * 3 + j;
        acc[j] = make_float2(v0 + ((y & 1) ? -v32 : v32), 0.f);
    }
    // pairs w, 64-w: conj twiddles -> re += S*c, im -= D*s
    #pragma unroll 4
    for (int w = 1; w < 32; w++) {
        float a = zz[w * 64 + c];
        float b = zz[(64 - w) * 64 + c];
        float S = a + b, D = a - b;
        #pragma unroll
        for (int j = 0; j < 3; j++) {
            float2 t = tw[(yg * 3 + j) * 64 + w];
            acc[j].x += S * t.x;
            acc[j].y -= D * t.y;
        }
    }
    #pragma unroll
    for (int j = 0; j < 3; j++)
        g_S1[((size_t)btf * 12 + yg * 3 + j) * 64 + c] = acc[j];
}

// ---------------- K2: DFT along H (32 -> 24), h/(32-h) pairing -------------
__global__ __launch_bounds__(256) void k2_hdft() {
    __shared__ float2 sA[2048];        // [h=32][c=64]
    __shared__ float2 tw[768];         // [f=24][h=32] packed (cos,sin)
    int bt = blockIdx.x;               // 0..127
    int xyy = blockIdx.y;              // 0..23 : xy*12 + y
    int xy = xyy / 12, y = xyy % 12;
    int tid = threadIdx.x;
    for (int e = tid; e < 2048; e += 256) {
        int hl = e >> 6, c = e & 63;
        sA[e] = g_S1[((size_t)(bt * 64 + xy * 32 + hl) * 12 + y) * 64 + c];
    }
    for (int i = tid; i < 768; i += 256) {
        int f = i >> 5, h = i & 31;
        int fx = (f < 12) ? f : (f + 8);
        float ang = (float)((fx * h) & 31) * (1.0f / 16.0f);
        tw[i] = make_float2(cospif(ang), sinpif(ang));
    }
    __syncthreads();
    int c = tid & 63, fg = tid >> 6;   // f = fg*6 + j
    // singles: h=0 (t=1), h=16 (t=((-1)^u, 0))
    float2 a0 = sA[c], a16 = sA[16 * 64 + c];
    float2 acc[6];
    #pragma unroll
    for (int j = 0; j < 6; j++) {
        int f = fg * 6 + j;
        int fx = (f < 12) ? f : (f + 8);
        float sg = (fx & 1) ? -1.f : 1.f;
        acc[j] = make_float2(a0.x + sg * a16.x, a0.y + sg * a16.y);
    }
    // pairs h, 32-h: re += Sx*c + Dy*s ; im += Sy*c - Dx*s
    #pragma unroll 3
    for (int hl = 1; hl < 16; hl++) {
        float2 a = sA[hl * 64 + c];
        float2 b = sA[(32 - hl) * 64 + c];
        float Sx = a.x + b.x, Sy = a.y + b.y;
        float Dx = a.x - b.x, Dy = a.y - b.y;
        #pragma unroll
        for (int j = 0; j < 6; j++) {
            float2 t = tw[(fg * 6 + j) * 32 + hl];
            acc[j].x += Sx * t.x + Dy * t.y;
            acc[j].y += Sy * t.x - Dx * t.y;
        }
    }
    #pragma unroll
    for (int j = 0; j < 6; j++) {
        int f = fg * 6 + j;
        g_XF[((size_t)(xy * NM + f * 12 + y) * 128 + bt) * 64 + c] = acc[j];
    }
}

// ---------------- K3: per-mode complex channel mixing (bt-pair fma2) -------
// Chunked staging (R14-style, 3 CTAs/SM) but bth folded into an in-kernel
// loop: the 56KB weight tile is staged ONCE and reused for both bt halves,
// halving the weight DRAM read (75.5 -> 37.7 MB).
__global__ __launch_bounds__(256, 3) void k3_mix(const float* __restrict__ wq,
                                                 const float* __restrict__ wk,
                                                 const float* __restrict__ wvx,
                                                 const float* __restrict__ wvy) {
    extern __shared__ __align__(16) char dyn[];
    float4* Wpk = (float4*)dyn;                       // [i=64][oh=64] 64KB
    float4* Apk = (float4*)(dyn + 65536);             // [pr=32][ii=8] 4KB
    float2* Ayp = (float2*)(dyn + 65536 + 4096);      // [pr=32][ii=8] 2KB
    const ulonglong2* Wpk64 = (const ulonglong2*)Wpk;
    const ulonglong2* Apk64 = (const ulonglong2*)Apk;
    const unsigned long long* Ayp64 = (const unsigned long long*)Ayp;
    int mode = blockIdx.x;             // 0..287
    int wi   = blockIdx.y;             // 0..3
    int xr = mode / 12, y = mode % 12;
    const float* wb = (wi == 0) ? wq : (wi == 1) ? wk : (wi == 2) ? wvx : wvy;
    int src = (wi == 3) ? 1 : 0;
    float2* outp = (wi == 0) ? g_QF : (wi == 1) ? g_KF : (wi == 2) ? g_VXF : g_VYF;
    int ri = (xr < 12) ? 0 : 1;
    int xx = (xr < 12) ? xr : xr - 12;
    // weight layout [region2][reim2][i=64][o=16][x=12][y=12][h=4]
    size_t moff = (size_t)ri * 1179648 + (size_t)xx * 48 + (size_t)y * 4;
    int tid = threadIdx.x;
    for (int e2 = tid; e2 < 1024; e2 += 256) {
        int i = e2 >> 4, o = e2 & 15;
        size_t a = moff + (size_t)i * 9216 + (size_t)o * 576;   // 16B aligned, 4 heads
        float4 rv = *(const float4*)&wb[a];
        float4 iv = *(const float4*)&wb[a + 589824];
        Wpk[i * 64 +  0 + o] = make_float4(rv.x, rv.x, iv.x, iv.x);
        Wpk[i * 64 + 16 + o] = make_float4(rv.y, rv.y, iv.y, iv.y);
        Wpk[i * 64 + 32 + o] = make_float4(rv.z, rv.z, iv.z, iv.z);
        Wpk[i * 64 + 48 + o] = make_float4(rv.w, rv.w, iv.w, iv.w);
    }
    int ohq = tid & 15;                // o index; h = k strided by 16
    int pairq = tid >> 4;              // 0..15 -> handles pairs pairq*2, pairq*2+1

    for (int bth = 0; bth < 2; bth++) {
        unsigned long long accRe[4][2], accIm[4][2];
        #pragma unroll
        for (int k = 0; k < 4; k++)
            #pragma unroll
            for (int p = 0; p < 2; p++) { accRe[k][p] = 0ull; accIm[k][p] = 0ull; }
        const float2* xsrc = g_XF + (size_t)(src * NM + mode) * 8192 + (size_t)bth * 4096;
        for (int chunk = 0; chunk < 8; chunk++) {
            __syncthreads();
            {   // stage 8-ii activation chunk: 1 element per thread
                int pr = tid >> 3, ii = tid & 7;
                float2 a0 = xsrc[(size_t)(pr * 2 + 0) * 64 + chunk * 8 + ii];
                float2 a1 = xsrc[(size_t)(pr * 2 + 1) * 64 + chunk * 8 + ii];
                Apk[tid] = make_float4(a0.x, a1.x, -a0.y, -a1.y);
                Ayp[tid] = make_float2(a0.y, a1.y);
            }
            __syncthreads();
            #pragma unroll
            for (int ii = 0; ii < 8; ii++) {
                int i = chunk * 8 + ii;
                ulonglong2 w0 = Wpk64[i * 64 + ohq];        // .x=(wx,wx) .y=(wy,wy)
                ulonglong2 w1 = Wpk64[i * 64 + ohq + 16];
                ulonglong2 w2 = Wpk64[i * 64 + ohq + 32];
                ulonglong2 w3 = Wpk64[i * 64 + ohq + 48];
                #pragma unroll
                for (int p = 0; p < 2; p++) {
                    ulonglong2 a = Apk64[(pairq * 2 + p) * 8 + ii];  // (ax0,ax1)|(-ay0,-ay1)
                    unsigned long long ap = Ayp64[(pairq * 2 + p) * 8 + ii]; // (ay0,ay1)
                    fma2(accRe[0][p], a.x, w0.x); fma2(accRe[0][p], a.y, w0.y);
                    fma2(accIm[0][p], a.x, w0.y); fma2(accIm[0][p], ap,  w0.x);
                    fma2(accRe[1][p], a.x, w1.x); fma2(accRe[1][p], a.y, w1.y);
                    fma2(accIm[1][p], a.x, w1.y); fma2(accIm[1][p], ap,  w1.x);
                    fma2(accRe[2][p], a.x, w2.x); fma2(accRe[2][p], a.y, w2.y);
                    fma2(accIm[2][p], a.x, w2.y); fma2(accIm[2][p], ap,  w2.x);
                    fma2(accRe[3][p], a.x, w3.x); fma2(accRe[3][p], a.y, w3.y);
                    fma2(accIm[3][p], a.x, w3.y); fma2(accIm[3][p], ap,  w3.x);
                }
            }
        }
        #pragma unroll
        for (int p = 0; p < 2; p++) {
            int pr = pairq * 2 + p;
            #pragma unroll
            for (int k = 0; k < 4; k++) {    // h = k, o = ohq
                float re0, re1, im0, im1;
                upk2(accRe[k][p], re0, re1);
                upk2(accIm[k][p], im0, im1);
                int bt0 = bth * 64 + pr * 2;
                int b0 = bt0 >> 5, t0 = bt0 & 31;
                int bt1 = bt0 + 1;
                int b1 = bt1 >> 5, t1 = bt1 & 31;
                outp[((size_t)((b0 * 4 + k) * 32 + t0) * NM + mode) * 16 + ohq] = make_float2(re0, im0);
                outp[((size_t)((b1 * 4 + k) * 32 + t1) * NM + mode) * 16 + ohq] = make_float2(re1, im1);
            }
        }
    }
}

// ---------------- K4: scores via Parseval (+ DC-column cross term) ---------
__global__ __launch_bounds__(256) void k4_scores() {
    __shared__ float2 sQ[3072];        // [pi=4][768] weighted Q chunk (24KB)
    __shared__ float2 sQc[1536];       // [pi=4][384] cross-term Q      (12KB)
    int blk = blockIdx.x;              // 0..127
    int bn = blk >> 3, pg = blk & 7;
    int tid = threadIdx.x, lane = tid & 31, warp = tid >> 5;
    for (int e = tid; e < 1536; e += 256) {
        int pi = e / 384, r = e - pi * 384;
        int xr = r >> 4, o = r & 15;
        float2 v = make_float2(0.f, 0.f);
        if (xr != 12) {
            int pxr = (xr == 0) ? 0 : (24 - xr);
            float2 q = g_QF[(size_t)(bn * 32 + pg * 4 + pi) * ROWF + pxr * 192 + o];
            v = make_float2(0.5f * q.x, 0.5f * q.y);
        }
        sQc[e] = v;
    }
    float acc[4][4];
    #pragma unroll
    for (int pi = 0; pi < 4; pi++)
        #pragma unroll
        for (int qi = 0; qi < 4; qi++) acc[pi][qi] = 0.f;
    int q0 = warp * 4;
    for (int ch = 0; ch < 6; ch++) {
        __syncthreads();
        for (int e = tid; e < 3072; e += 256) {
            int pi = e / 768, r = e - pi * 768;
            int j = ch * 768 + r;
            float2 q = g_QF[(size_t)(bn * 32 + pg * 4 + pi) * ROWF + j];
            float w = (((j >> 4) % 12) == 0) ? 0.5f : 2.0f;
            sQ[e] = make_float2(q.x * w, q.y * w);
        }
        __syncthreads();
        #pragma unroll 4
        for (int r = lane; r < 768; r += 32) {
            int j = ch * 768 + r;
            float2 kk0 = g_KF[(size_t)(bn * 32 + q0 + 0) * ROWF + j];
            float2 kk1 = g_KF[(size_t)(bn * 32 + q0 + 1) * ROWF + j];
            float2 kk2 = g_KF[(size_t)(bn * 32 + q0 + 2) * ROWF + j];
            float2 kk3 = g_KF[(size_t)(bn * 32 + q0 + 3) * ROWF + j];
            #pragma unroll
            for (int pi = 0; pi < 4; pi++) {
                float2 qw = sQ[pi * 768 + r];
                acc[pi][0] += qw.x * kk0.x + qw.y * kk0.y;
                acc[pi][1] += qw.x * kk1.x + qw.y * kk1.y;
                acc[pi][2] += qw.x * kk2.x + qw.y * kk2.y;
                acc[pi][3] += qw.x * kk3.x + qw.y * kk3.y;
            }
        }
    }
    #pragma unroll 2
    for (int r = lane; r < 384; r += 32) {
        int xr = r >> 4, o = r & 15;
        size_t koff = (size_t)xr * 192 + o;
        float2 kk0 = g_KF[(size_t)(bn * 32 + q0 + 0) * ROWF + koff];
        float2 kk1 = g_KF[(size_t)(bn * 32 + q0 + 1) * ROWF + koff];
        float2 kk2 = g_KF[(size_t)(bn * 32 + q0 + 2) * ROWF + koff];
        float2 kk3 = g_KF[(size_t)(bn * 32 + q0 + 3) * ROWF + koff];
        #pragma unroll
        for (int pi = 0; pi < 4; pi++) {
            float2 qc = sQc[pi * 384 + r];
            acc[pi][0] += qc.x * kk0.x - qc.y * kk0.y;
            acc[pi][1] += qc.x * kk1.x - qc.y * kk1.y;
            acc[pi][2] += qc.x * kk2.x - qc.y * kk2.y;
            acc[pi][3] += qc.x * kk3.x - qc.y * kk3.y;
        }
    }
    #pragma unroll
    for (int pi = 0; pi < 4; pi++)
        #pragma unroll
        for (int qi = 0; qi < 4; qi++) {
            float s = acc[pi][qi];
            #pragma unroll
            for (int off = 16; off; off >>= 1) s += __shfl_down_sync(0xffffffffu, s, off);
            if (lane == 0)
                g_SC[bn * 1024 + (pg * 4 + pi) * 32 + q0 + qi] = s * (1.0f / (2048.0f * 4096.0f));
        }
}

// ---------------- K5: Fourier-domain T-mixing of V -------------------------
__global__ __launch_bounds__(256) void k5_mixv() {
    __shared__ float ssc[256];         // 8 p x 32 q
    int bn = blockIdx.x, half = blockIdx.y, pg = blockIdx.z;
    int tid = threadIdx.x;
    ssc[tid] = g_SC[bn * 1024 + pg * 256 + tid];
    __syncthreads();
    const float4* V = (const float4*)((half == 0) ? g_VXF : g_VYF);
    float4* MFp = (float4*)g_MF;       // row stride 2304 float4
    for (int ei = 0; ei < 9; ei++) {
        int e = tid + ei * 256;        // 0..2303
        float4 acc[8];
        #pragma unroll
        for (int pp = 0; pp < 8; pp++) acc[pp] = make_float4(0.f, 0.f, 0.f, 0.f);
        for (int q = 0; q < 32; q++) {
            float4 v = V[(size_t)(bn * 32 + q) * 2304 + e];
            #pragma unroll
            for (int pp = 0; pp < 8; pp++) {
                float s = ssc[pp * 32 + q];
                acc[pp].x += s * v.x; acc[pp].y += s * v.y;
                acc[pp].z += s * v.z; acc[pp].w += s * v.w;
            }
        }
        #pragma unroll
        for (int pp = 0; pp < 8; pp++) {
            int p = pg * 8 + pp;
            MFp[((size_t)(bn * 32 + p) * 2 + half) * 2304 + e] = acc[pp];
        }
    }
}

// ---------------- K6: inverse transform + gaussian, symmetry-paired --------
__global__ __launch_bounds__(256) void k6_inv(float* __restrict__ out) {
    __shared__ float2 Ms[2304];        // [f=24][v=12][oo=8]
    __shared__ float2 G[3072];         // [h=32][v=12][oo=8]
    __shared__ float2 cstab[32];
    __shared__ float wtc[64], wts[64];
    int bnp = blockIdx.x;              // 0..511 = (b*4+n)*32+p
    int half = blockIdx.y;             // 0..1
    int og = blockIdx.z;               // 0..1 (o-group of 8)
    int tid = threadIdx.x;
    if (tid < 64) { wtc[tid] = cospif(tid * (1.0f / 32.0f)); wts[tid] = sinpif(tid * (1.0f / 32.0f)); }
    else if (tid < 96) { int j = tid - 64; cstab[j] = make_float2(cospif(j * (1.0f / 16.0f)), sinpif(j * (1.0f / 16.0f))); }
    const float2* src = g_MF + ((size_t)bnp * 2 + half) * ROWF;
    for (int e = tid; e < 2304; e += 256) {
        int f = e / 96; int r = e - f * 96; int v = r >> 3; int oo = r & 7;
        Ms[e] = src[(f * 12 + v) * 16 + og * 8 + oo];
    }
    __syncthreads();
    // phase A: u-inverse with u <-> 32-u pairing (f=u pairs f=24-u, u=1..11;
    // singles f=0 (u=0) and f=12 (u=20)).
    #pragma unroll
    for (int r = 0; r < 3; r++) {
        int task = tid + r * 256;      // 768 tasks
        int oo = task & 7, v = (task >> 3) % 12, hg = task / 96;
        int h0 = hg * 4;
        // f=0: t=1 for all h
        float2 m0 = Ms[v * 8 + oo];
        float2 a0 = m0, a1 = m0, a2 = m0, a3 = m0;
        // f=12 single (u=20)
        {
            float2 m = Ms[12 * 96 + v * 8 + oo];
            float2 t0 = cstab[(20 * h0) & 31];
            float2 t1 = cstab[(20 * (h0 + 1)) & 31];
            float2 t2 = cstab[(20 * (h0 + 2)) & 31];
            float2 t3 = cstab[(20 * (h0 + 3)) & 31];
            a0.x += m.x*t0.x - m.y*t0.y; a0.y += m.x*t0.y + m.y*t0.x;
            a1.x += m.x*t1.x - m.y*t1.y; a1.y += m.x*t1.y + m.y*t1.x;
            a2.x += m.x*t2.x - m.y*t2.y; a2.y += m.x*t2.y + m.y*t2.x;
            a3.x += m.x*t3.x - m.y*t3.y; a3.y += m.x*t3.y + m.y*t3.x;
        }
        // pairs: u=1..11, partner f'=24-u (u'=32-u, conj twiddle)
        #pragma unroll
        for (int u = 1; u <= 11; u++) {
            float2 mA = Ms[u * 96 + v * 8 + oo];
            float2 mB = Ms[(24 - u) * 96 + v * 8 + oo];
            float Sx = mA.x + mB.x, Sy = mA.y + mB.y;
            float Dx = mA.x - mB.x, Dy = mA.y - mB.y;
            float2 t0 = cstab[(u * h0) & 31];
            float2 t1 = cstab[(u * (h0 + 1)) & 31];
            float2 t2 = cstab[(u * (h0 + 2)) & 31];
            float2 t3 = cstab[(u * (h0 + 3)) & 31];
            a0.x += Sx*t0.x - Dy*t0.y; a0.y += Dx*t0.y + Sy*t0.x;
            a1.x += Sx*t1.x - Dy*t1.y; a1.y += Dx*t1.y + Sy*t1.x;
            a2.x += Sx*t2.x - Dy*t2.y; a2.y += Dx*t2.y + Sy*t2.x;
            a3.x += Sx*t3.x - Dy*t3.y; a3.y += Dx*t3.y + Sy*t3.x;
        }
        float wv = (v == 0) ? (1.0f / 2048.0f) : (2.0f / 2048.0f);
        int base = h0 * 96 + v * 8 + oo;
        G[base      ] = make_float2(a0.x * wv, a0.y * wv);
        G[base +  96] = make_float2(a1.x * wv, a1.y * wv);
        G[base + 192] = make_float2(a2.x * wv, a2.y * wv);
        G[base + 288] = make_float2(a3.x * wv, a3.y * wv);
    }
    __syncthreads();
    // phase B: w-inverse via even/odd-v split (w+32 twiddle = (-1)^v * w twiddle)
    int oo = tid & 7;
    int wb = tid >> 3;                 // 0..31 ; covers w = wb and wb+32
    float tc[12], ts[12];
    #pragma unroll
    for (int v = 0; v < 12; v++) {
        tc[v] = wtc[(v * wb) & 63];
        ts[v] = wts[(v * wb) & 63];
    }
    size_t obase = (size_t)bnp * 65536 + og * 8 + oo;
    for (int h = 0; h < 32; h++) {
        float E = 0.f, O = 0.f;
        #pragma unroll
        for (int v = 0; v < 12; v += 2) {
            float2 ge = G[h * 96 + v * 8 + oo];
            E += ge.x * tc[v] - ge.y * ts[v];
            float2 go = G[h * 96 + (v + 1) * 8 + oo];
            O += go.x * tc[v + 1] - go.y * ts[v + 1];
        }
        float aw0 = E + O, aw1 = E - O;
        int m0 = (half * 32 + h) * 64 + wb;
        out[obase + (size_t)m0 * 16]        = aw0 * g_G[m0];
        out[obase + (size_t)(m0 + 32) * 16] = aw1 * g_G[m0 + 32];
    }
}

extern "C" void kernel_launch(void* const* d_in, const int* in_sizes, int n_in,
                              void* d_out, int out_size) {
    const float* z   = (const float*)d_in[0];
    const float* wq  = (const float*)d_in[1];
    const float* wk  = (const float*)d_in[2];
    const float* wvx = (const float*)d_in[3];
    const float* wvy = (const float*)d_in[4];
    float* out = (float*)d_out;
    (void)in_sizes; (void)n_in; (void)out_size;

    static int attr_done = 0;
    if (!attr_done) {
        cudaFuncSetAttribute(k3_mix, cudaFuncAttributeMaxDynamicSharedMemorySize, 71680);
        attr_done = 1;
    }

    k0_init<<<1, 256>>>();
    k1_wdft<<<8192, 256>>>(z);
    k2_hdft<<<dim3(128, 24), 256>>>();
    k3_mix<<<dim3(288, 4), 256, 71680>>>(wq, wk, wvx, wvy);
    k4_scores<<<128, 256>>>();
    k5_mixv<<<dim3(16, 2, 4), 256>>>();
    k6_inv<<<dim3(512, 2, 2), 256>>>(out);
}